// round 15
// baseline (speedup 1.0000x reference)
#include <cuda_runtime.h>
#include <cuda_fp16.h>
#include <cstdint>
#include <cstddef>

#define VOCAB 32000
#define HID   1024
#define EMB   512
#define RANK  64
#define BATCH 16
#define SEQLEN 256
#define NTOK  (BATCH*SEQLEN)
#define KA    1024
#define KB    1024

#define RNN_BLOCKS 128
#define NCHUNKS 4
#define STEPS_PER_CHUNK (SEQLEN/NCHUNKS)

// smem floats: Vp 8192, Asm 9216, Cs 520, gs 1040, red 8448
#define OFF_VP 0
#define OFF_A  8192
#define OFF_C  17408
#define OFF_G  17928
#define OFF_R  18968
#define RNN_SMEM_FLOATS 27416
// padded request: 150 KB so RNN(150)+decoder(82) > 228 KB -> no co-residence
#define RNN_SMEM_BYTES  (150*1024)

__device__ __align__(16) float g_XU[NTOK*HID];
__device__ __align__(16) float g_XB[NTOK*RANK];
__device__ __align__(16) float g_h[2][BATCH*HID];          // row-major (phase-1)
__device__ __align__(16) float g_hP[2][4][HID*4];          // plane: [bg2][j*4 + b&3]
__device__ __align__(16) float g_gbuf[BATCH*RANK];
__device__ __align__(16) __half g_Acat[(size_t)NTOK*KA];
__device__ __align__(16) __half g_Bcat[(size_t)VOCAB*KB];
__device__ unsigned g_bar_arrive = 0;
__device__ unsigned g_bar_gen    = 0;

__device__ __forceinline__ void grid_bar() {
    __threadfence();
    __syncthreads();
    if (threadIdx.x == 0) {
        volatile unsigned* genp = (volatile unsigned*)&g_bar_gen;
        unsigned gen = *genp;
        unsigned arrived = atomicAdd(&g_bar_arrive, 1u);
        if (arrived == RNN_BLOCKS - 1) {
            atomicExch(&g_bar_arrive, 0u);
            __threadfence();
            atomicAdd(&g_bar_gen, 1u);
        } else {
            while (*genp == gen) { }
            __threadfence();
        }
    }
    __syncthreads();
}

__device__ __forceinline__ unsigned long long pk2(float lo, float hi) {
    unsigned long long r;
    asm("mov.b64 %0, {%1, %2};" : "=l"(r) : "f"(lo), "f"(hi));
    return r;
}
__device__ __forceinline__ void fma2(unsigned long long& d, unsigned long long a, unsigned long long b) {
    asm("fma.rn.f32x2 %0, %1, %2, %0;" : "+l"(d) : "l"(a), "l"(b));
}
__device__ __forceinline__ float2 upk2(unsigned long long v) {
    float2 r;
    asm("mov.b64 {%0, %1}, %2;" : "=f"(r.x), "=f"(r.y) : "l"(v));
    return r;
}

// ======================= precompute: XU, XB ================================
template <int N_, bool HAS_BIAS>
__global__ __launch_bounds__(256) void gather_gemm(const int* __restrict__ inp,
                                                   const float* __restrict__ emb,
                                                   const float* __restrict__ W,
                                                   const float* __restrict__ bias) {
    __shared__ float As[16][65];
    __shared__ float Bs[16][68];
    __shared__ int   toks[64];
    float* outp = (N_ == RANK) ? g_XB : g_XU;

    const int tid = threadIdx.x;
    const int m0 = blockIdx.x * 64, n0 = blockIdx.y * 64;
    if (tid < 64) {
        int m = m0 + tid;
        toks[tid] = inp[(m & 15) * SEQLEN + (m >> 4)];
    }
    __syncthreads();

    const int ty = tid >> 4, tx = tid & 15;
    const int am = tid >> 2, akq = tid & 3;
    const int bk = tid >> 4, bn = tid & 15;
    float acc[4][4] = {};

    for (int k0 = 0; k0 < EMB; k0 += 16) {
        float4 av = *(const float4*)&emb[(size_t)toks[am] * EMB + k0 + akq * 4];
        float4 bv = *(const float4*)&W[(size_t)(k0 + bk) * N_ + n0 + bn * 4];
        __syncthreads();
        As[akq*4+0][am] = av.x; As[akq*4+1][am] = av.y;
        As[akq*4+2][am] = av.z; As[akq*4+3][am] = av.w;
        *(float4*)&Bs[bk][bn*4] = bv;
        __syncthreads();
#pragma unroll
        for (int kk = 0; kk < 16; kk++) {
            float a0 = As[kk][ty*4+0], a1 = As[kk][ty*4+1];
            float a2 = As[kk][ty*4+2], a3 = As[kk][ty*4+3];
            float4 b4 = *(const float4*)&Bs[kk][tx*4];
            acc[0][0] += a0*b4.x; acc[0][1] += a0*b4.y; acc[0][2] += a0*b4.z; acc[0][3] += a0*b4.w;
            acc[1][0] += a1*b4.x; acc[1][1] += a1*b4.y; acc[1][2] += a1*b4.z; acc[1][3] += a1*b4.w;
            acc[2][0] += a2*b4.x; acc[2][1] += a2*b4.y; acc[2][2] += a2*b4.z; acc[2][3] += a2*b4.w;
            acc[3][0] += a3*b4.x; acc[3][1] += a3*b4.y; acc[3][2] += a3*b4.z; acc[3][3] += a3*b4.w;
        }
    }

    float4 bb = make_float4(0.f,0.f,0.f,0.f);
    if (HAS_BIAS) bb = *(const float4*)&bias[n0 + tx*4];
#pragma unroll
    for (int i = 0; i < 4; i++) {
        int m = m0 + ty*4 + i;
        float4 o = make_float4(acc[i][0]+bb.x, acc[i][1]+bb.y, acc[i][2]+bb.z, acc[i][3]+bb.w);
        *(float4*)&outp[(size_t)m * N_ + n0 + tx*4] = o;
    }
}

// ======================= recurrence (round-10 proven, chunked) =============
__global__ __launch_bounds__(256) void rnn_kernel(const float* __restrict__ A,
                                                  const float* __restrict__ C,
                                                  const float* __restrict__ V,
                                                  int t0, int t1) {
    extern __shared__ float sm[];
    float* Vp  = sm + OFF_VP;  // permuted: [(((cc*2+ks)*4+i)*32+kg2)*4 + q]
    float* Asm = sm + OFF_A;   // [1024][9]
    float* Cs  = sm + OFF_C;   // [8][65]
    float* gs  = sm + OFF_G;   // [16][65]
    float* red = sm + OFF_R;   // [256][33]

    const int c = blockIdx.x, tid = threadIdx.x;
    const int col0  = c * 8;
    const int rbase = (c & 7) * 8;
    const int bmine = c >> 3;

    for (int idx = tid; idx < 8192; idx += 256) {
        int cc = idx & 7, j = idx >> 3;
        int ksj = j >> 9, ij = (j >> 7) & 3, qj = (j >> 5) & 3, kj = j & 31;
        Vp[(((cc*2 + ksj)*4 + ij)*32 + kj)*4 + qj] = V[(size_t)j*HID + col0 + cc];
        Asm[j*9 + cc] = A[j*RANK + rbase + cc];
    }
    for (int idx = tid; idx < 512; idx += 256) {
        int ci = idx >> 6, r = idx & 63;
        Cs[ci*65 + r] = C[(col0 + ci)*RANK + r];
    }
    if (t0 == 0 && tid < 128) {
        g_h[0][c*128 + tid] = 0.0f;
        ((float*)g_hP[0])[c*128 + tid] = 0.0f;
    }
    __syncthreads();
    grid_bar();

    const int lane = tid & 31, w = tid >> 5;
    const int bg2 = tid >> 6, ks = (tid >> 5) & 1, kg2 = tid & 31;
    const int b128 = tid >> 3, ci128 = tid & 7;

    for (int t = t0; t < t1; t++) {
        const int p = t & 1;
        float xu = 0.f, xb = 0.f;
        if (tid < 128)
            xu = __ldcg(&g_XU[((size_t)t*BATCH + b128)*HID + col0 + ci128]);
        if (lane == 0)
            xb = __ldcg(&g_XB[((size_t)t*BATCH + bmine)*RANK + rbase + w]);

        // phase 1: g[bmine, rbase+w] = (h@A) * XB
        {
            const float* hrow = g_h[p] + bmine * HID;
            float s = 0.f;
#pragma unroll 8
            for (int j = lane; j < HID; j += 32)
                s += __ldcg(hrow + j) * Asm[j*9 + w];
#pragma unroll
            for (int off = 16; off; off >>= 1)
                s += __shfl_xor_sync(0xffffffffu, s, off);
            if (lane == 0)
                __stcg(&g_gbuf[bmine*RANK + rbase + w], s * xb);
        }
        grid_bar();

        // phase 2
        {
            for (int idx = tid; idx < 1024; idx += 256)
                gs[(idx >> 6)*65 + (idx & 63)] = __ldcg(&g_gbuf[idx]);

            const float4* hp = (const float4*)g_hP[p][bg2];
            unsigned long long acc2[8][2];
#pragma unroll
            for (int cc = 0; cc < 8; cc++) { acc2[cc][0] = 0ull; acc2[cc][1] = 0ull; }

#pragma unroll
            for (int i = 0; i < 4; i++) {
                const int jb = ks*512 + i*128 + kg2;
                float4 hv[4], vv[8];
#pragma unroll
                for (int q = 0; q < 4; q++)
                    hv[q] = __ldcg(&hp[jb + q*32]);
#pragma unroll
                for (int cc = 0; cc < 8; cc++)
                    vv[cc] = *(const float4*)&Vp[(((cc*2 + ks)*4 + i)*32 + kg2)*4];

                unsigned long long h01[4], h23[4];
#pragma unroll
                for (int q = 0; q < 4; q++) {
                    h01[q] = pk2(hv[q].x, hv[q].y);
                    h23[q] = pk2(hv[q].z, hv[q].w);
                }
#pragma unroll
                for (int cc = 0; cc < 8; cc++) {
                    const float* vq = (const float*)&vv[cc];
#pragma unroll
                    for (int q = 0; q < 4; q++) {
                        unsigned long long vd = pk2(vq[q], vq[q]);
                        fma2(acc2[cc][0], vd, h01[q]);
                        fma2(acc2[cc][1], vd, h23[q]);
                    }
                }
            }
#pragma unroll
            for (int cc = 0; cc < 8; cc++) {
                float2 a0 = upk2(acc2[cc][0]), a1 = upk2(acc2[cc][1]);
                red[tid*33 + cc*4 + 0] = a0.x;
                red[tid*33 + cc*4 + 1] = a0.y;
                red[tid*33 + cc*4 + 2] = a1.x;
                red[tid*33 + cc*4 + 3] = a1.y;
            }
            __syncthreads();

            if (tid < 128) {
                const int b = b128, ci = ci128;
                const int bgo = b >> 2, slot = ci*4 + (b & 3);
                const int ii = col0 + ci;
                float s = 0.f;
#pragma unroll 16
                for (int u = 0; u < 64; u++) {
                    int src = (bgo*2 + (u >> 5))*32 + (u & 31);
                    s += red[src*33 + slot];
                }
#pragma unroll 16
                for (int r = 0; r < RANK; r++)
                    s += gs[b*65 + r] * Cs[ci*65 + r];
                s += xu;
                float hn = tanhf(s);
                __stcg(&g_h[p^1][b*HID + ii], hn);
                __stcg(&g_hP[p^1][b >> 2][ii*4 + (b & 3)], hn);
                g_Acat[((size_t)t*BATCH + b)*KA + ii] = __float2half(hn);
            }
        }
        grid_bar();
    }
}

// ======================= W operand preparation =============================
__global__ __launch_bounds__(256) void conv_W(const float* __restrict__ W) {
    __shared__ float tile[32][33];
    const int bx = blockIdx.x, by = blockIdx.y;
    const int tx = threadIdx.x & 31, ty = threadIdx.x >> 5;
    int n = bx*32 + tx;
#pragma unroll
    for (int r = 0; r < 32; r += 8) {
        int k = by*32 + ty + r;
        tile[ty + r][tx] = W[(size_t)k*VOCAB + n];
    }
    __syncthreads();
#pragma unroll
    for (int r = 0; r < 32; r += 8) {
        int n2 = bx*32 + ty + r;
        int k2 = by*32 + tx;
        g_Bcat[(size_t)n2*KB + k2] = __float2half(tile[tx][ty + r]);
    }
}

// ======================= HMMA decoder GEMM (chunked M) =====================
#define DEC_STAGES 4
#define DEC_STG_BYTES 20480
#define DEC_SMEM (512 + DEC_STAGES*DEC_STG_BYTES)
#define DEC_NCHUNK (KA/32)

__device__ __forceinline__ uint32_t s2u(const void* p) {
    uint32_t a;
    asm("{ .reg .u64 t; cvta.to.shared.u64 t, %1; cvt.u32.u64 %0, t; }" : "=r"(a) : "l"(p));
    return a;
}
__device__ __forceinline__ void cp16(uint32_t dst, const void* src) {
    asm volatile("cp.async.cg.shared.global [%0], [%1], 16;" :: "r"(dst), "l"(src));
}
__device__ __forceinline__ void cp_commit() {
    asm volatile("cp.async.commit_group;" ::: "memory");
}
template <int N> __device__ __forceinline__ void cp_wait() {
    asm volatile("cp.async.wait_group %0;" :: "n"(N) : "memory");
}
__device__ __forceinline__ void ldmx4(uint32_t* r, uint32_t a) {
    asm volatile("ldmatrix.sync.aligned.m8n8.x4.shared.b16 {%0,%1,%2,%3}, [%4];"
        : "=r"(r[0]), "=r"(r[1]), "=r"(r[2]), "=r"(r[3]) : "r"(a));
}
__device__ __forceinline__ void mma16816(float* c, const uint32_t* a, uint32_t b0, uint32_t b1) {
    asm volatile("mma.sync.aligned.m16n8k16.row.col.f32.f16.f16.f32 "
        "{%0,%1,%2,%3}, {%4,%5,%6,%7}, {%8,%9}, {%0,%1,%2,%3};"
        : "+f"(c[0]), "+f"(c[1]), "+f"(c[2]), "+f"(c[3])
        : "r"(a[0]), "r"(a[1]), "r"(a[2]), "r"(a[3]), "r"(b0), "r"(b1));
}

__device__ __forceinline__ void dec_load(uint32_t base, const char* Ag, const char* Bg,
                                         int kc, int r_, int seg) {
    const size_t koff = (size_t)kc * 64;
    cp16(base + r_*80 + seg*16,        Ag + (size_t)r_      * (KA*2) + koff + seg*16);
    cp16(base + (r_+64)*80 + seg*16,   Ag + (size_t)(r_+64) * (KA*2) + koff + seg*16);
    cp16(base + 10240 + r_*80 + seg*16,      Bg + (size_t)r_      * (KB*2) + koff + seg*16);
    cp16(base + 10240 + (r_+64)*80 + seg*16, Bg + (size_t)(r_+64) * (KB*2) + koff + seg*16);
}

__global__ void __launch_bounds__(256, 2) decoder_hmma(const float* __restrict__ bias,
                                                       float* __restrict__ out,
                                                       int mblk0) {
    extern __shared__ __align__(16) char smem[];
    float* sbias = (float*)smem;
    const uint32_t D0 = s2u(smem) + 512;
    const int tid = threadIdx.x;
    const int wid = tid >> 5, lid = tid & 31;
    const int m0 = (blockIdx.x + mblk0) * 128, n0 = blockIdx.y * 128;
    const int wm = wid >> 1, wn = wid & 1;

    if (tid < 128) sbias[tid] = bias[n0 + tid];

    const char* Ag = (const char*)(g_Acat + (size_t)m0 * KA);
    const char* Bg = (const char*)(g_Bcat + (size_t)n0 * KB);
    const int r_ = tid >> 2, seg = tid & 3;

    float acc[2][8][4];
#pragma unroll
    for (int i = 0; i < 2; i++)
#pragma unroll
        for (int j = 0; j < 8; j++)
#pragma unroll
            for (int q = 0; q < 4; q++) acc[i][j][q] = 0.f;

#pragma unroll
    for (int s = 0; s < DEC_STAGES - 1; s++) {
        dec_load(D0 + s*DEC_STG_BYTES, Ag, Bg, s, r_, seg);
        cp_commit();
    }

    const int quad = lid >> 3, r8 = lid & 7;
    const uint32_t a_row = wm*32 + (quad & 1)*8 + r8;
    const uint32_t a_kb  = (quad >> 1) * 16;
    const uint32_t b_row = wn*64 + (quad >> 1)*8 + r8;
    const uint32_t b_kb  = (quad & 1) * 16;

    for (int kc = 0; kc < DEC_NCHUNK; kc++) {
        const int s = kc & (DEC_STAGES - 1);
        cp_wait<DEC_STAGES - 2>();
        __syncthreads();
        if (kc + DEC_STAGES - 1 < DEC_NCHUNK) {
            dec_load(D0 + ((kc + DEC_STAGES - 1) & (DEC_STAGES - 1))*DEC_STG_BYTES,
                     Ag, Bg, kc + DEC_STAGES - 1, r_, seg);
        }
        cp_commit();

        const uint32_t sA = D0 + s * DEC_STG_BYTES;
        const uint32_t sB = sA + 10240;
#pragma unroll
        for (int kk = 0; kk < 2; kk++) {
            uint32_t A0[4], A1[4], Bf[4][4];
            uint32_t aaddr = sA + a_row*80 + kk*32 + a_kb;
            ldmx4(A0, aaddr);
            ldmx4(A1, aaddr + 16*80);
            uint32_t baddr = sB + b_row*80 + kk*32 + b_kb;
#pragma unroll
            for (int p = 0; p < 4; p++) ldmx4(Bf[p], baddr + p*16*80);
#pragma unroll
            for (int ni = 0; ni < 8; ni++) {
                uint32_t b0 = Bf[ni >> 1][(ni & 1)*2 + 0];
                uint32_t b1 = Bf[ni >> 1][(ni & 1)*2 + 1];
                mma16816(acc[0][ni], A0, b0, b1);
                mma16816(acc[1][ni], A1, b0, b1);
            }
        }
    }
    cp_wait<0>();

    const int mrow0 = m0 + wm*32 + (lid >> 2);
    const int ncol0 = wn*64 + 2*(lid & 3);
#pragma unroll
    for (int mi = 0; mi < 2; mi++) {
        int mA = mrow0 + mi*16, mB = mA + 8;
        float* oA = out + (size_t)((mA & 15)*SEQLEN + (mA >> 4)) * VOCAB + n0;
        float* oB = out + (size_t)((mB & 15)*SEQLEN + (mB >> 4)) * VOCAB + n0;
#pragma unroll
        for (int ni = 0; ni < 8; ni++) {
            int nn = ncol0 + ni*8;
            float2 vA = make_float2(acc[mi][ni][0] + sbias[nn], acc[mi][ni][1] + sbias[nn+1]);
            float2 vB = make_float2(acc[mi][ni][2] + sbias[nn], acc[mi][ni][3] + sbias[nn+1]);
            *(float2*)(oA + nn) = vA;
            *(float2*)(oB + nn) = vB;
        }
    }
}

// ======================= launch ============================================
extern "C" void kernel_launch(void* const* d_in, const int* in_sizes, int n_in,
                              void* d_out, int out_size) {
    const int*   inp = (const int*)d_in[0];
    const float* emb = (const float*)d_in[1];
    const float* A   = (const float*)d_in[2];
    const float* B   = (const float*)d_in[3];
    const float* C   = (const float*)d_in[4];
    const float* U   = (const float*)d_in[5];
    const float* V   = (const float*)d_in[6];
    const float* dv  = (const float*)d_in[7];
    const float* Wd  = (const float*)d_in[8];
    const float* bd  = (const float*)d_in[9];
    float* out = (float*)d_out;

    // one-time stream/event setup (first call happens outside graph capture)
    static cudaStream_t sHi = nullptr, sLo = nullptr;
    static cudaEvent_t ev0, evR[NCHUNKS], evEnd;
    if (sHi == nullptr) {
        int prLo, prHi;
        cudaDeviceGetStreamPriorityRange(&prLo, &prHi);
        cudaStreamCreateWithPriority(&sHi, cudaStreamNonBlocking, prHi);
        cudaStreamCreateWithPriority(&sLo, cudaStreamNonBlocking, prLo);
        cudaEventCreateWithFlags(&ev0, cudaEventDisableTiming);
        for (int i = 0; i < NCHUNKS; i++)
            cudaEventCreateWithFlags(&evR[i], cudaEventDisableTiming);
        cudaEventCreateWithFlags(&evEnd, cudaEventDisableTiming);
        cudaFuncSetAttribute(rnn_kernel, cudaFuncAttributeMaxDynamicSharedMemorySize,
                             RNN_SMEM_BYTES);
        cudaFuncSetAttribute(decoder_hmma, cudaFuncAttributeMaxDynamicSharedMemorySize,
                             DEC_SMEM);
    }

    // fork both worker streams from the capture-origin stream
    cudaEventRecord(ev0, 0);
    cudaStreamWaitEvent(sHi, ev0, 0);
    cudaStreamWaitEvent(sLo, ev0, 0);

    // low stream: W conversion (needed before first decoder chunk)
    conv_W<<<dim3(VOCAB/32, HID/32), 256, 0, sLo>>>(Wd);

    // high stream: precompute then chunked recurrence
    dim3 gXU(NTOK/64, HID/64);
    gather_gemm<HID, true><<<gXU, 256, 0, sHi>>>(inp, emb, U, dv);
    dim3 gXB(NTOK/64, RANK/64);
    gather_gemm<RANK, false><<<gXB, 256, 0, sHi>>>(inp, emb, B, nullptr);

    for (int cch = 0; cch < NCHUNKS; cch++) {
        rnn_kernel<<<RNN_BLOCKS, 256, RNN_SMEM_BYTES, sHi>>>(
            A, C, V, cch*STEPS_PER_CHUNK, (cch + 1)*STEPS_PER_CHUNK);
        cudaEventRecord(evR[cch], sHi);
    }

    // low stream: decoder chunks, each gated on its RNN chunk
    for (int cch = 0; cch < NCHUNKS; cch++) {
        cudaStreamWaitEvent(sLo, evR[cch], 0);
        decoder_hmma<<<dim3((NTOK/128)/NCHUNKS, VOCAB/128), 256, DEC_SMEM, sLo>>>(
            bd, out, cch * ((NTOK/128)/NCHUNKS));
    }

    // join both streams back to the origin stream
    cudaEventRecord(evEnd, sLo);
    cudaStreamWaitEvent(0, evR[NCHUNKS-1], 0);
    cudaStreamWaitEvent(0, evEnd, 0);
}

// round 16
// speedup vs baseline: 1.3719x; 1.3719x over previous
#include <cuda_runtime.h>
#include <cuda_fp16.h>
#include <cstdint>
#include <cstddef>

#define VOCAB 32000
#define HID   1024
#define EMB   512
#define RANK  64
#define BATCH 16
#define SEQLEN 256
#define NTOK  (BATCH*SEQLEN)
#define KA    1024
#define KB    1024

#define RNN_BLOCKS 128
#define NCHUNKS 4
#define STEPS_PER_CHUNK (SEQLEN/NCHUNKS)

// smem floats: Vp 8192, As2 512, Cs 520, gs 1040, red 8448, hbuf 144
#define OFF_VP 0
#define OFF_A2 8192
#define OFF_C  8704
#define OFF_G  9224
#define OFF_R  10264
#define OFF_HB 18712
#define RNN_SMEM_FLOATS 18856
#define RNN_SMEM_BYTES  (RNN_SMEM_FLOATS*4)

__device__ __align__(16) float g_XU[NTOK*HID];
__device__ __align__(16) float g_XB[NTOK*RANK];
__device__ __align__(16) float g_hP[2][4][HID*4];        // plane: [bg2][j*4 + b&3]
__device__ __align__(16) float g_ApP[3][8][BATCH*RANK];  // h@A group partials, triple buffer
__device__ __align__(16) __half g_Acat[(size_t)NTOK*KA];
__device__ __align__(16) __half g_Bcat[(size_t)VOCAB*KB];
__device__ unsigned g_bar_arrive = 0;
__device__ unsigned g_bar_gen    = 0;

__device__ __forceinline__ void grid_bar() {
    __threadfence();
    __syncthreads();
    if (threadIdx.x == 0) {
        volatile unsigned* genp = (volatile unsigned*)&g_bar_gen;
        unsigned gen = *genp;
        unsigned arrived = atomicAdd(&g_bar_arrive, 1u);
        if (arrived == RNN_BLOCKS - 1) {
            atomicExch(&g_bar_arrive, 0u);
            __threadfence();
            atomicAdd(&g_bar_gen, 1u);
        } else {
            while (*genp == gen) { }
            __threadfence();
        }
    }
    __syncthreads();
}

__device__ __forceinline__ unsigned long long pk2(float lo, float hi) {
    unsigned long long r;
    asm("mov.b64 %0, {%1, %2};" : "=l"(r) : "f"(lo), "f"(hi));
    return r;
}
__device__ __forceinline__ void fma2(unsigned long long& d, unsigned long long a, unsigned long long b) {
    asm("fma.rn.f32x2 %0, %1, %2, %0;" : "+l"(d) : "l"(a), "l"(b));
}
__device__ __forceinline__ float2 upk2(unsigned long long v) {
    float2 r;
    asm("mov.b64 {%0, %1}, %2;" : "=f"(r.x), "=f"(r.y) : "l"(v));
    return r;
}

// ======================= precompute: XU, XB ================================
template <int N_, bool HAS_BIAS>
__global__ __launch_bounds__(256) void gather_gemm(const int* __restrict__ inp,
                                                   const float* __restrict__ emb,
                                                   const float* __restrict__ W,
                                                   const float* __restrict__ bias) {
    __shared__ float As[16][65];
    __shared__ float Bs[16][68];
    __shared__ int   toks[64];
    float* outp = (N_ == RANK) ? g_XB : g_XU;

    const int tid = threadIdx.x;
    const int m0 = blockIdx.x * 64, n0 = blockIdx.y * 64;
    if (tid < 64) {
        int m = m0 + tid;
        toks[tid] = inp[(m & 15) * SEQLEN + (m >> 4)];
    }
    __syncthreads();

    const int ty = tid >> 4, tx = tid & 15;
    const int am = tid >> 2, akq = tid & 3;
    const int bk = tid >> 4, bn = tid & 15;
    float acc[4][4] = {};

    for (int k0 = 0; k0 < EMB; k0 += 16) {
        float4 av = *(const float4*)&emb[(size_t)toks[am] * EMB + k0 + akq * 4];
        float4 bv = *(const float4*)&W[(size_t)(k0 + bk) * N_ + n0 + bn * 4];
        __syncthreads();
        As[akq*4+0][am] = av.x; As[akq*4+1][am] = av.y;
        As[akq*4+2][am] = av.z; As[akq*4+3][am] = av.w;
        *(float4*)&Bs[bk][bn*4] = bv;
        __syncthreads();
#pragma unroll
        for (int kk = 0; kk < 16; kk++) {
            float a0 = As[kk][ty*4+0], a1 = As[kk][ty*4+1];
            float a2 = As[kk][ty*4+2], a3 = As[kk][ty*4+3];
            float4 b4 = *(const float4*)&Bs[kk][tx*4];
            acc[0][0] += a0*b4.x; acc[0][1] += a0*b4.y; acc[0][2] += a0*b4.z; acc[0][3] += a0*b4.w;
            acc[1][0] += a1*b4.x; acc[1][1] += a1*b4.y; acc[1][2] += a1*b4.z; acc[1][3] += a1*b4.w;
            acc[2][0] += a2*b4.x; acc[2][1] += a2*b4.y; acc[2][2] += a2*b4.z; acc[2][3] += a2*b4.w;
            acc[3][0] += a3*b4.x; acc[3][1] += a3*b4.y; acc[3][2] += a3*b4.z; acc[3][3] += a3*b4.w;
        }
    }

    float4 bb = make_float4(0.f,0.f,0.f,0.f);
    if (HAS_BIAS) bb = *(const float4*)&bias[n0 + tx*4];
#pragma unroll
    for (int i = 0; i < 4; i++) {
        int m = m0 + ty*4 + i;
        float4 o = make_float4(acc[i][0]+bb.x, acc[i][1]+bb.y, acc[i][2]+bb.z, acc[i][3]+bb.w);
        *(float4*)&outp[(size_t)m * N_ + n0 + tx*4] = o;
    }
}

// ============ recurrence: 1 grid barrier / step, group-partial Ap ==========
__global__ __launch_bounds__(256) void rnn_kernel(const float* __restrict__ A,
                                                  const float* __restrict__ C,
                                                  const float* __restrict__ V,
                                                  int t0, int t1) {
    extern __shared__ float sm[];
    float* Vp   = sm + OFF_VP;  // permuted V slice
    float* As2  = sm + OFF_A2;  // [8][64] A rows col0..col0+8
    float* Cs   = sm + OFF_C;   // [8][65]
    float* gs   = sm + OFF_G;   // [16][65]
    float* red  = sm + OFF_R;   // [256][33]
    float* hbuf = sm + OFF_HB;  // [16][9]

    const int c = blockIdx.x, tid = threadIdx.x;
    const int col0 = c * 8;
    const int grp  = c & 7;

    for (int idx = tid; idx < 8192; idx += 256) {
        int cc = idx & 7, j = idx >> 3;
        int ksj = j >> 9, ij = (j >> 7) & 3, qj = (j >> 5) & 3, kj = j & 31;
        Vp[(((cc*2 + ksj)*4 + ij)*32 + kj)*4 + qj] = V[(size_t)j*HID + col0 + cc];
    }
    for (int idx = tid; idx < 512; idx += 256) {
        int ci = idx >> 6, r = idx & 63;
        As2[idx] = A[(col0 + ci)*RANK + r];
        Cs[ci*65 + r] = C[(col0 + ci)*RANK + r];
    }
    if (t0 == 0) {
        if (tid < 128) ((float*)g_hP[0])[c*128 + tid] = 0.0f;
        int gtid = c*256 + tid;
        if (gtid < 3*8*BATCH*RANK) ((float*)g_ApP)[gtid] = 0.0f;
    }
    __syncthreads();
    grid_bar();

    const int bg2 = tid >> 6, ks = (tid >> 5) & 1, kg2 = tid & 31;
    const int b128 = tid >> 3, ci128 = tid & 7;
    const int sidx = tid * 4, sb = sidx >> 6, sr = sidx & 63;

    for (int t = t0; t < t1; t++) {
        const int p = t & 1;

        // stage gs = (sum of 8 Ap partials)[t%3] * XB ; zero (t+2)%3 partials
        {
            float4 ap = __ldcg((const float4*)&g_ApP[t % 3][0][sidx]);
#pragma unroll
            for (int pg = 1; pg < 8; pg++) {
                float4 v = __ldcg((const float4*)&g_ApP[t % 3][pg][sidx]);
                ap.x += v.x; ap.y += v.y; ap.z += v.z; ap.w += v.w;
            }
            float4 xb = __ldcg((const float4*)&g_XB[(size_t)t*1024 + sidx]);
            gs[sb*65 + sr + 0] = ap.x * xb.x;
            gs[sb*65 + sr + 1] = ap.y * xb.y;
            gs[sb*65 + sr + 2] = ap.z * xb.z;
            gs[sb*65 + sr + 3] = ap.w * xb.w;
            if (c < 8)
                *(float4*)&g_ApP[(t + 2) % 3][c][sidx] = make_float4(0.f, 0.f, 0.f, 0.f);
        }
        float xu = 0.f;
        if (tid < 128)
            xu = __ldcg(&g_XU[((size_t)t*BATCH + b128)*HID + col0 + ci128]);

        // mainloop: h@V from plane-transposed global h
        const float4* hp = (const float4*)g_hP[p][bg2];
        unsigned long long acc2[8][2];
#pragma unroll
        for (int cc = 0; cc < 8; cc++) { acc2[cc][0] = 0ull; acc2[cc][1] = 0ull; }

#pragma unroll
        for (int i = 0; i < 4; i++) {
            const int jb = ks*512 + i*128 + kg2;
            float4 hv[4], vv[8];
#pragma unroll
            for (int q = 0; q < 4; q++)
                hv[q] = __ldcg(&hp[jb + q*32]);
#pragma unroll
            for (int cc = 0; cc < 8; cc++)
                vv[cc] = *(const float4*)&Vp[(((cc*2 + ks)*4 + i)*32 + kg2)*4];

            unsigned long long h01[4], h23[4];
#pragma unroll
            for (int q = 0; q < 4; q++) {
                h01[q] = pk2(hv[q].x, hv[q].y);
                h23[q] = pk2(hv[q].z, hv[q].w);
            }
#pragma unroll
            for (int cc = 0; cc < 8; cc++) {
                const float* vq = (const float*)&vv[cc];
#pragma unroll
                for (int q = 0; q < 4; q++) {
                    unsigned long long vd = pk2(vq[q], vq[q]);
                    fma2(acc2[cc][0], vd, h01[q]);
                    fma2(acc2[cc][1], vd, h23[q]);
                }
            }
        }
#pragma unroll
        for (int cc = 0; cc < 8; cc++) {
            float2 a0 = upk2(acc2[cc][0]), a1 = upk2(acc2[cc][1]);
            red[tid*33 + cc*4 + 0] = a0.x;
            red[tid*33 + cc*4 + 1] = a0.y;
            red[tid*33 + cc*4 + 2] = a1.x;
            red[tid*33 + cc*4 + 3] = a1.y;
        }
        __syncthreads();

        // combine: h_new = tanh(XU + g@C^T + h@V)
        if (tid < 128) {
            const int b = b128, ci = ci128;
            const int bgo = b >> 2, slot = ci*4 + (b & 3);
            const int ii = col0 + ci;
            float s = 0.f;
#pragma unroll 16
            for (int u = 0; u < 64; u++) {
                int src = (bgo*2 + (u >> 5))*32 + (u & 31);
                s += red[src*33 + slot];
            }
#pragma unroll 16
            for (int r = 0; r < RANK; r++)
                s += gs[b*65 + r] * Cs[ci*65 + r];
            s += xu;
            float hn = tanhf(s);
            __stcg(&g_hP[p^1][b >> 2][ii*4 + (b & 3)], hn);
            g_Acat[((size_t)t*BATCH + b)*KA + ii] = __float2half(hn);
            hbuf[b*9 + ci] = hn;
        }
        __syncthreads();

        // push next step's Ap partial: group buffer grp, 16-way contention
        {
            float s0 = 0.f, s1 = 0.f, s2 = 0.f, s3 = 0.f;
#pragma unroll
            for (int ci = 0; ci < 8; ci++) {
                float hv = hbuf[sb*9 + ci];
                float4 av = *(const float4*)&As2[ci*64 + sr];
                s0 += hv*av.x; s1 += hv*av.y; s2 += hv*av.z; s3 += hv*av.w;
            }
            float* apw = g_ApP[(t + 1) % 3][grp];
            atomicAdd(&apw[sidx + 0], s0);
            atomicAdd(&apw[sidx + 1], s1);
            atomicAdd(&apw[sidx + 2], s2);
            atomicAdd(&apw[sidx + 3], s3);
        }
        grid_bar();
    }
}

// ======================= W operand preparation =============================
__global__ __launch_bounds__(256) void conv_W(const float* __restrict__ W) {
    __shared__ float tile[32][33];
    const int bx = blockIdx.x, by = blockIdx.y;
    const int tx = threadIdx.x & 31, ty = threadIdx.x >> 5;
    int n = bx*32 + tx;
#pragma unroll
    for (int r = 0; r < 32; r += 8) {
        int k = by*32 + ty + r;
        tile[ty + r][tx] = W[(size_t)k*VOCAB + n];
    }
    __syncthreads();
#pragma unroll
    for (int r = 0; r < 32; r += 8) {
        int n2 = bx*32 + ty + r;
        int k2 = by*32 + tx;
        g_Bcat[(size_t)n2*KB + k2] = __float2half(tile[tx][ty + r]);
    }
}

// ======================= HMMA decoder GEMM (chunked M) =====================
#define DEC_STAGES 4
#define DEC_STG_BYTES 20480
#define DEC_SMEM (512 + DEC_STAGES*DEC_STG_BYTES)
#define DEC_NCHUNK (KA/32)

__device__ __forceinline__ uint32_t s2u(const void* p) {
    uint32_t a;
    asm("{ .reg .u64 t; cvta.to.shared.u64 t, %1; cvt.u32.u64 %0, t; }" : "=r"(a) : "l"(p));
    return a;
}
__device__ __forceinline__ void cp16(uint32_t dst, const void* src) {
    asm volatile("cp.async.cg.shared.global [%0], [%1], 16;" :: "r"(dst), "l"(src));
}
__device__ __forceinline__ void cp_commit() {
    asm volatile("cp.async.commit_group;" ::: "memory");
}
template <int N> __device__ __forceinline__ void cp_wait() {
    asm volatile("cp.async.wait_group %0;" :: "n"(N) : "memory");
}
__device__ __forceinline__ void ldmx4(uint32_t* r, uint32_t a) {
    asm volatile("ldmatrix.sync.aligned.m8n8.x4.shared.b16 {%0,%1,%2,%3}, [%4];"
        : "=r"(r[0]), "=r"(r[1]), "=r"(r[2]), "=r"(r[3]) : "r"(a));
}
__device__ __forceinline__ void mma16816(float* c, const uint32_t* a, uint32_t b0, uint32_t b1) {
    asm volatile("mma.sync.aligned.m16n8k16.row.col.f32.f16.f16.f32 "
        "{%0,%1,%2,%3}, {%4,%5,%6,%7}, {%8,%9}, {%0,%1,%2,%3};"
        : "+f"(c[0]), "+f"(c[1]), "+f"(c[2]), "+f"(c[3])
        : "r"(a[0]), "r"(a[1]), "r"(a[2]), "r"(a[3]), "r"(b0), "r"(b1));
}

__device__ __forceinline__ void dec_load(uint32_t base, const char* Ag, const char* Bg,
                                         int kc, int r_, int seg) {
    const size_t koff = (size_t)kc * 64;
    cp16(base + r_*80 + seg*16,        Ag + (size_t)r_      * (KA*2) + koff + seg*16);
    cp16(base + (r_+64)*80 + seg*16,   Ag + (size_t)(r_+64) * (KA*2) + koff + seg*16);
    cp16(base + 10240 + r_*80 + seg*16,      Bg + (size_t)r_      * (KB*2) + koff + seg*16);
    cp16(base + 10240 + (r_+64)*80 + seg*16, Bg + (size_t)(r_+64) * (KB*2) + koff + seg*16);
}

__global__ void __launch_bounds__(256, 2) decoder_hmma(const float* __restrict__ bias,
                                                       float* __restrict__ out,
                                                       int mblk0) {
    extern __shared__ __align__(16) char smem[];
    float* sbias = (float*)smem;
    const uint32_t D0 = s2u(smem) + 512;
    const int tid = threadIdx.x;
    const int wid = tid >> 5, lid = tid & 31;
    const int m0 = (blockIdx.x + mblk0) * 128, n0 = blockIdx.y * 128;
    const int wm = wid >> 1, wn = wid & 1;

    if (tid < 128) sbias[tid] = bias[n0 + tid];

    const char* Ag = (const char*)(g_Acat + (size_t)m0 * KA);
    const char* Bg = (const char*)(g_Bcat + (size_t)n0 * KB);
    const int r_ = tid >> 2, seg = tid & 3;

    float acc[2][8][4];
#pragma unroll
    for (int i = 0; i < 2; i++)
#pragma unroll
        for (int j = 0; j < 8; j++)
#pragma unroll
            for (int q = 0; q < 4; q++) acc[i][j][q] = 0.f;

#pragma unroll
    for (int s = 0; s < DEC_STAGES - 1; s++) {
        dec_load(D0 + s*DEC_STG_BYTES, Ag, Bg, s, r_, seg);
        cp_commit();
    }

    const int quad = lid >> 3, r8 = lid & 7;
    const uint32_t a_row = wm*32 + (quad & 1)*8 + r8;
    const uint32_t a_kb  = (quad >> 1) * 16;
    const uint32_t b_row = wn*64 + (quad >> 1)*8 + r8;
    const uint32_t b_kb  = (quad & 1) * 16;

    for (int kc = 0; kc < DEC_NCHUNK; kc++) {
        const int s = kc & (DEC_STAGES - 1);
        cp_wait<DEC_STAGES - 2>();
        __syncthreads();
        if (kc + DEC_STAGES - 1 < DEC_NCHUNK) {
            dec_load(D0 + ((kc + DEC_STAGES - 1) & (DEC_STAGES - 1))*DEC_STG_BYTES,
                     Ag, Bg, kc + DEC_STAGES - 1, r_, seg);
        }
        cp_commit();

        const uint32_t sA = D0 + s * DEC_STG_BYTES;
        const uint32_t sB = sA + 10240;
#pragma unroll
        for (int kk = 0; kk < 2; kk++) {
            uint32_t A0[4], A1[4], Bf[4][4];
            uint32_t aaddr = sA + a_row*80 + kk*32 + a_kb;
            ldmx4(A0, aaddr);
            ldmx4(A1, aaddr + 16*80);
            uint32_t baddr = sB + b_row*80 + kk*32 + b_kb;
#pragma unroll
            for (int p = 0; p < 4; p++) ldmx4(Bf[p], baddr + p*16*80);
#pragma unroll
            for (int ni = 0; ni < 8; ni++) {
                uint32_t b0 = Bf[ni >> 1][(ni & 1)*2 + 0];
                uint32_t b1 = Bf[ni >> 1][(ni & 1)*2 + 1];
                mma16816(acc[0][ni], A0, b0, b1);
                mma16816(acc[1][ni], A1, b0, b1);
            }
        }
    }
    cp_wait<0>();

    const int mrow0 = m0 + wm*32 + (lid >> 2);
    const int ncol0 = wn*64 + 2*(lid & 3);
#pragma unroll
    for (int mi = 0; mi < 2; mi++) {
        int mA = mrow0 + mi*16, mB = mA + 8;
        float* oA = out + (size_t)((mA & 15)*SEQLEN + (mA >> 4)) * VOCAB + n0;
        float* oB = out + (size_t)((mB & 15)*SEQLEN + (mB >> 4)) * VOCAB + n0;
#pragma unroll
        for (int ni = 0; ni < 8; ni++) {
            int nn = ncol0 + ni*8;
            float2 vA = make_float2(acc[mi][ni][0] + sbias[nn], acc[mi][ni][1] + sbias[nn+1]);
            float2 vB = make_float2(acc[mi][ni][2] + sbias[nn], acc[mi][ni][3] + sbias[nn+1]);
            *(float2*)(oA + nn) = vA;
            *(float2*)(oB + nn) = vB;
        }
    }
}

// ======================= launch ============================================
extern "C" void kernel_launch(void* const* d_in, const int* in_sizes, int n_in,
                              void* d_out, int out_size) {
    const int*   inp = (const int*)d_in[0];
    const float* emb = (const float*)d_in[1];
    const float* A   = (const float*)d_in[2];
    const float* B   = (const float*)d_in[3];
    const float* C   = (const float*)d_in[4];
    const float* U   = (const float*)d_in[5];
    const float* V   = (const float*)d_in[6];
    const float* dv  = (const float*)d_in[7];
    const float* Wd  = (const float*)d_in[8];
    const float* bd  = (const float*)d_in[9];
    float* out = (float*)d_out;

    // one-time stream/event setup (first call happens outside graph capture)
    static cudaStream_t sHi = nullptr, sLo = nullptr;
    static cudaEvent_t ev0, evR[NCHUNKS], evEnd;
    if (sHi == nullptr) {
        int prLo, prHi;
        cudaDeviceGetStreamPriorityRange(&prLo, &prHi);
        cudaStreamCreateWithPriority(&sHi, cudaStreamNonBlocking, prHi);
        cudaStreamCreateWithPriority(&sLo, cudaStreamNonBlocking, prLo);
        cudaEventCreateWithFlags(&ev0, cudaEventDisableTiming);
        for (int i = 0; i < NCHUNKS; i++)
            cudaEventCreateWithFlags(&evR[i], cudaEventDisableTiming);
        cudaEventCreateWithFlags(&evEnd, cudaEventDisableTiming);
        cudaFuncSetAttribute(rnn_kernel, cudaFuncAttributeMaxDynamicSharedMemorySize,
                             RNN_SMEM_BYTES);
        cudaFuncSetAttribute(decoder_hmma, cudaFuncAttributeMaxDynamicSharedMemorySize,
                             DEC_SMEM);
    }

    // fork both worker streams from the capture-origin stream
    cudaEventRecord(ev0, 0);
    cudaStreamWaitEvent(sHi, ev0, 0);
    cudaStreamWaitEvent(sLo, ev0, 0);

    // low stream: W conversion (needed before first decoder chunk)
    conv_W<<<dim3(VOCAB/32, HID/32), 256, 0, sLo>>>(Wd);

    // high stream: precompute then chunked recurrence
    dim3 gXU(NTOK/64, HID/64);
    gather_gemm<HID, true><<<gXU, 256, 0, sHi>>>(inp, emb, U, dv);
    dim3 gXB(NTOK/64, RANK/64);
    gather_gemm<RANK, false><<<gXB, 256, 0, sHi>>>(inp, emb, B, nullptr);

    for (int cch = 0; cch < NCHUNKS; cch++) {
        rnn_kernel<<<RNN_BLOCKS, 256, RNN_SMEM_BYTES, sHi>>>(
            A, C, V, cch*STEPS_PER_CHUNK, (cch + 1)*STEPS_PER_CHUNK);
        cudaEventRecord(evR[cch], sHi);
    }

    // low stream: decoder chunks, each gated on its RNN chunk
    for (int cch = 0; cch < NCHUNKS; cch++) {
        cudaStreamWaitEvent(sLo, evR[cch], 0);
        decoder_hmma<<<dim3((NTOK/128)/NCHUNKS, VOCAB/128), 256, DEC_SMEM, sLo>>>(
            bd, out, cch * ((NTOK/128)/NCHUNKS));
    }

    // join both streams back to the origin stream
    cudaEventRecord(evEnd, sLo);
    cudaStreamWaitEvent(0, evR[NCHUNKS-1], 0);
    cudaStreamWaitEvent(0, evEnd, 0);
}

// round 17
// speedup vs baseline: 1.4199x; 1.0350x over previous
#include <cuda_runtime.h>
#include <cuda_fp16.h>
#include <cstdint>
#include <cstddef>

#define VOCAB 32000
#define HID   1024
#define EMB   512
#define RANK  64
#define BATCH 16
#define SEQLEN 256
#define NTOK  (BATCH*SEQLEN)
#define KA    1024
#define KB    1024

#define RNN_BLOCKS 128
#define NCHUNKS 4
#define STEPS_PER_CHUNK (SEQLEN/NCHUNKS)
#define BARS_PER_CHUNK (1 + STEPS_PER_CHUNK)

// smem floats: Vp 8192, As2 512, Cs 520, gs 1040, red 8448, hbuf 144
#define OFF_VP 0
#define OFF_A2 8192
#define OFF_C  8704
#define OFF_G  9224
#define OFF_R  10264
#define OFF_HB 18712
#define RNN_SMEM_FLOATS 18856
#define RNN_SMEM_BYTES  (RNN_SMEM_FLOATS*4)

__device__ __align__(16) float g_XU[NTOK*HID];
__device__ __align__(16) float g_XB[NTOK*RANK];
__device__ __align__(16) float g_hP[2][4][HID*4];        // plane: [bg2][j*4 + b&3]
__device__ __align__(16) float g_ApP[3][8][BATCH*RANK];  // h@A group partials, triple buffer
__device__ __align__(16) __half g_Acat[(size_t)NTOK*KA];
__device__ __align__(16) __half g_Bcat[(size_t)VOCAB*KB];
__device__ unsigned g_count = 0;                          // monotonic barrier counter

__global__ void reset_bar() { g_count = 0; }

// RED-arrive monotonic grid barrier: target tracked per-CTA in a register.
__device__ __forceinline__ void gbar(unsigned& target) {
    __threadfence();
    __syncthreads();
    if (threadIdx.x == 0) {
        atomicAdd(&g_count, 1u);          // result unused -> REDG
        target += RNN_BLOCKS;
        volatile unsigned* vc = &g_count;
        while (*vc < target) { }
        __threadfence();
    }
    __syncthreads();
}

__device__ __forceinline__ unsigned long long pk2(float lo, float hi) {
    unsigned long long r;
    asm("mov.b64 %0, {%1, %2};" : "=l"(r) : "f"(lo), "f"(hi));
    return r;
}
__device__ __forceinline__ void fma2(unsigned long long& d, unsigned long long a, unsigned long long b) {
    asm("fma.rn.f32x2 %0, %1, %2, %0;" : "+l"(d) : "l"(a), "l"(b));
}
__device__ __forceinline__ float2 upk2(unsigned long long v) {
    float2 r;
    asm("mov.b64 {%0, %1}, %2;" : "=f"(r.x), "=f"(r.y) : "l"(v));
    return r;
}

// ======================= precompute: XU, XB ================================
template <int N_, bool HAS_BIAS>
__global__ __launch_bounds__(256) void gather_gemm(const int* __restrict__ inp,
                                                   const float* __restrict__ emb,
                                                   const float* __restrict__ W,
                                                   const float* __restrict__ bias) {
    __shared__ float As[16][65];
    __shared__ float Bs[16][68];
    __shared__ int   toks[64];
    float* outp = (N_ == RANK) ? g_XB : g_XU;

    const int tid = threadIdx.x;
    const int m0 = blockIdx.x * 64, n0 = blockIdx.y * 64;
    if (tid < 64) {
        int m = m0 + tid;
        toks[tid] = inp[(m & 15) * SEQLEN + (m >> 4)];
    }
    __syncthreads();

    const int ty = tid >> 4, tx = tid & 15;
    const int am = tid >> 2, akq = tid & 3;
    const int bk = tid >> 4, bn = tid & 15;
    float acc[4][4] = {};

    for (int k0 = 0; k0 < EMB; k0 += 16) {
        float4 av = *(const float4*)&emb[(size_t)toks[am] * EMB + k0 + akq * 4];
        float4 bv = *(const float4*)&W[(size_t)(k0 + bk) * N_ + n0 + bn * 4];
        __syncthreads();
        As[akq*4+0][am] = av.x; As[akq*4+1][am] = av.y;
        As[akq*4+2][am] = av.z; As[akq*4+3][am] = av.w;
        *(float4*)&Bs[bk][bn*4] = bv;
        __syncthreads();
#pragma unroll
        for (int kk = 0; kk < 16; kk++) {
            float a0 = As[kk][ty*4+0], a1 = As[kk][ty*4+1];
            float a2 = As[kk][ty*4+2], a3 = As[kk][ty*4+3];
            float4 b4 = *(const float4*)&Bs[kk][tx*4];
            acc[0][0] += a0*b4.x; acc[0][1] += a0*b4.y; acc[0][2] += a0*b4.z; acc[0][3] += a0*b4.w;
            acc[1][0] += a1*b4.x; acc[1][1] += a1*b4.y; acc[1][2] += a1*b4.z; acc[1][3] += a1*b4.w;
            acc[2][0] += a2*b4.x; acc[2][1] += a2*b4.y; acc[2][2] += a2*b4.z; acc[2][3] += a2*b4.w;
            acc[3][0] += a3*b4.x; acc[3][1] += a3*b4.y; acc[3][2] += a3*b4.z; acc[3][3] += a3*b4.w;
        }
    }

    float4 bb = make_float4(0.f,0.f,0.f,0.f);
    if (HAS_BIAS) bb = *(const float4*)&bias[n0 + tx*4];
#pragma unroll
    for (int i = 0; i < 4; i++) {
        int m = m0 + ty*4 + i;
        float4 o = make_float4(acc[i][0]+bb.x, acc[i][1]+bb.y, acc[i][2]+bb.z, acc[i][3]+bb.w);
        *(float4*)&outp[(size_t)m * N_ + n0 + tx*4] = o;
    }
}

// ============ recurrence: 1 RED-barrier / step, group-partial Ap ===========
__global__ __launch_bounds__(256) void rnn_kernel(const float* __restrict__ A,
                                                  const float* __restrict__ C,
                                                  const float* __restrict__ V,
                                                  int t0, int t1, unsigned bar_base) {
    extern __shared__ float sm[];
    float* Vp   = sm + OFF_VP;  // permuted V slice
    float* As2  = sm + OFF_A2;  // [8][64] A rows col0..col0+8
    float* Cs   = sm + OFF_C;   // [8][65]
    float* gs   = sm + OFF_G;   // [16][65]
    float* red  = sm + OFF_R;   // [256][33]
    float* hbuf = sm + OFF_HB;  // [16][9]

    const int c = blockIdx.x, tid = threadIdx.x;
    const int col0 = c * 8;
    const int grp  = c & 7;
    unsigned bar_target = bar_base;

    for (int idx = tid; idx < 8192; idx += 256) {
        int cc = idx & 7, j = idx >> 3;
        int ksj = j >> 9, ij = (j >> 7) & 3, qj = (j >> 5) & 3, kj = j & 31;
        Vp[(((cc*2 + ksj)*4 + ij)*32 + kj)*4 + qj] = V[(size_t)j*HID + col0 + cc];
    }
    for (int idx = tid; idx < 512; idx += 256) {
        int ci = idx >> 6, r = idx & 63;
        As2[idx] = A[(col0 + ci)*RANK + r];
        Cs[ci*65 + r] = C[(col0 + ci)*RANK + r];
    }
    if (t0 == 0) {
        if (tid < 128) ((float*)g_hP[0])[c*128 + tid] = 0.0f;
        int gtid = c*256 + tid;
        if (gtid < 3*8*BATCH*RANK) ((float*)g_ApP)[gtid] = 0.0f;
    }
    __syncthreads();
    gbar(bar_target);

    const int bg2 = tid >> 6, ks = (tid >> 5) & 1, kg2 = tid & 31;
    const int b128 = tid >> 3, ci128 = tid & 7;
    const int sidx = tid * 4, sb = sidx >> 6, sr = sidx & 63;

    for (int t = t0; t < t1; t++) {
        const int p = t & 1;

        // stage gs = (sum of 8 Ap partials)[t%3] * XB ; zero (t+2)%3 partials
        {
            float4 ap = __ldcg((const float4*)&g_ApP[t % 3][0][sidx]);
#pragma unroll
            for (int pg = 1; pg < 8; pg++) {
                float4 v = __ldcg((const float4*)&g_ApP[t % 3][pg][sidx]);
                ap.x += v.x; ap.y += v.y; ap.z += v.z; ap.w += v.w;
            }
            float4 xb = __ldcg((const float4*)&g_XB[(size_t)t*1024 + sidx]);
            gs[sb*65 + sr + 0] = ap.x * xb.x;
            gs[sb*65 + sr + 1] = ap.y * xb.y;
            gs[sb*65 + sr + 2] = ap.z * xb.z;
            gs[sb*65 + sr + 3] = ap.w * xb.w;
            if (c < 8)
                *(float4*)&g_ApP[(t + 2) % 3][c][sidx] = make_float4(0.f, 0.f, 0.f, 0.f);
        }
        float xu = 0.f;
        if (tid < 128)
            xu = __ldcg(&g_XU[((size_t)t*BATCH + b128)*HID + col0 + ci128]);

        // mainloop: h@V — prefetch ALL 16 h-vectors first (MLP=16)
        const float4* hp = (const float4*)g_hP[p][bg2];
        float4 hv[4][4];
#pragma unroll
        for (int i = 0; i < 4; i++)
#pragma unroll
            for (int q = 0; q < 4; q++)
                hv[i][q] = __ldcg(&hp[ks*512 + i*128 + kg2 + q*32]);

        unsigned long long acc2[8][2];
#pragma unroll
        for (int cc = 0; cc < 8; cc++) { acc2[cc][0] = 0ull; acc2[cc][1] = 0ull; }

#pragma unroll
        for (int i = 0; i < 4; i++) {
            float4 vv[8];
#pragma unroll
            for (int cc = 0; cc < 8; cc++)
                vv[cc] = *(const float4*)&Vp[(((cc*2 + ks)*4 + i)*32 + kg2)*4];

            unsigned long long h01[4], h23[4];
#pragma unroll
            for (int q = 0; q < 4; q++) {
                h01[q] = pk2(hv[i][q].x, hv[i][q].y);
                h23[q] = pk2(hv[i][q].z, hv[i][q].w);
            }
#pragma unroll
            for (int cc = 0; cc < 8; cc++) {
                const float* vq = (const float*)&vv[cc];
#pragma unroll
                for (int q = 0; q < 4; q++) {
                    unsigned long long vd = pk2(vq[q], vq[q]);
                    fma2(acc2[cc][0], vd, h01[q]);
                    fma2(acc2[cc][1], vd, h23[q]);
                }
            }
        }
#pragma unroll
        for (int cc = 0; cc < 8; cc++) {
            float2 a0 = upk2(acc2[cc][0]), a1 = upk2(acc2[cc][1]);
            red[tid*33 + cc*4 + 0] = a0.x;
            red[tid*33 + cc*4 + 1] = a0.y;
            red[tid*33 + cc*4 + 2] = a1.x;
            red[tid*33 + cc*4 + 3] = a1.y;
        }
        __syncthreads();

        // combine: h_new = tanh(XU + g@C^T + h@V)
        if (tid < 128) {
            const int b = b128, ci = ci128;
            const int bgo = b >> 2, slot = ci*4 + (b & 3);
            const int ii = col0 + ci;
            float s = 0.f;
#pragma unroll 16
            for (int u = 0; u < 64; u++) {
                int src = (bgo*2 + (u >> 5))*32 + (u & 31);
                s += red[src*33 + slot];
            }
#pragma unroll 16
            for (int r = 0; r < RANK; r++)
                s += gs[b*65 + r] * Cs[ci*65 + r];
            s += xu;
            float hn = tanhf(s);
            __stcg(&g_hP[p^1][b >> 2][ii*4 + (b & 3)], hn);
            g_Acat[((size_t)t*BATCH + b)*KA + ii] = __float2half(hn);
            hbuf[b*9 + ci] = hn;
        }
        __syncthreads();

        // push next step's Ap partial: group buffer grp, 16-way contention
        {
            float s0 = 0.f, s1 = 0.f, s2 = 0.f, s3 = 0.f;
#pragma unroll
            for (int ci = 0; ci < 8; ci++) {
                float hv1 = hbuf[sb*9 + ci];
                float4 av = *(const float4*)&As2[ci*64 + sr];
                s0 += hv1*av.x; s1 += hv1*av.y; s2 += hv1*av.z; s3 += hv1*av.w;
            }
            float* apw = g_ApP[(t + 1) % 3][grp];
            atomicAdd(&apw[sidx + 0], s0);
            atomicAdd(&apw[sidx + 1], s1);
            atomicAdd(&apw[sidx + 2], s2);
            atomicAdd(&apw[sidx + 3], s3);
        }
        gbar(bar_target);
    }
}

// ======================= W operand preparation =============================
__global__ __launch_bounds__(256) void conv_W(const float* __restrict__ W) {
    __shared__ float tile[32][33];
    const int bx = blockIdx.x, by = blockIdx.y;
    const int tx = threadIdx.x & 31, ty = threadIdx.x >> 5;
    int n = bx*32 + tx;
#pragma unroll
    for (int r = 0; r < 32; r += 8) {
        int k = by*32 + ty + r;
        tile[ty + r][tx] = W[(size_t)k*VOCAB + n];
    }
    __syncthreads();
#pragma unroll
    for (int r = 0; r < 32; r += 8) {
        int n2 = bx*32 + ty + r;
        int k2 = by*32 + tx;
        g_Bcat[(size_t)n2*KB + k2] = __float2half(tile[tx][ty + r]);
    }
}

// ======================= HMMA decoder GEMM (chunked M) =====================
#define DEC_STAGES 4
#define DEC_STG_BYTES 20480
#define DEC_SMEM (512 + DEC_STAGES*DEC_STG_BYTES)
#define DEC_NCHUNK (KA/32)

__device__ __forceinline__ uint32_t s2u(const void* p) {
    uint32_t a;
    asm("{ .reg .u64 t; cvta.to.shared.u64 t, %1; cvt.u32.u64 %0, t; }" : "=r"(a) : "l"(p));
    return a;
}
__device__ __forceinline__ void cp16(uint32_t dst, const void* src) {
    asm volatile("cp.async.cg.shared.global [%0], [%1], 16;" :: "r"(dst), "l"(src));
}
__device__ __forceinline__ void cp_commit() {
    asm volatile("cp.async.commit_group;" ::: "memory");
}
template <int N> __device__ __forceinline__ void cp_wait() {
    asm volatile("cp.async.wait_group %0;" :: "n"(N) : "memory");
}
__device__ __forceinline__ void ldmx4(uint32_t* r, uint32_t a) {
    asm volatile("ldmatrix.sync.aligned.m8n8.x4.shared.b16 {%0,%1,%2,%3}, [%4];"
        : "=r"(r[0]), "=r"(r[1]), "=r"(r[2]), "=r"(r[3]) : "r"(a));
}
__device__ __forceinline__ void mma16816(float* c, const uint32_t* a, uint32_t b0, uint32_t b1) {
    asm volatile("mma.sync.aligned.m16n8k16.row.col.f32.f16.f16.f32 "
        "{%0,%1,%2,%3}, {%4,%5,%6,%7}, {%8,%9}, {%0,%1,%2,%3};"
        : "+f"(c[0]), "+f"(c[1]), "+f"(c[2]), "+f"(c[3])
        : "r"(a[0]), "r"(a[1]), "r"(a[2]), "r"(a[3]), "r"(b0), "r"(b1));
}

__device__ __forceinline__ void dec_load(uint32_t base, const char* Ag, const char* Bg,
                                         int kc, int r_, int seg) {
    const size_t koff = (size_t)kc * 64;
    cp16(base + r_*80 + seg*16,        Ag + (size_t)r_      * (KA*2) + koff + seg*16);
    cp16(base + (r_+64)*80 + seg*16,   Ag + (size_t)(r_+64) * (KA*2) + koff + seg*16);
    cp16(base + 10240 + r_*80 + seg*16,      Bg + (size_t)r_      * (KB*2) + koff + seg*16);
    cp16(base + 10240 + (r_+64)*80 + seg*16, Bg + (size_t)(r_+64) * (KB*2) + koff + seg*16);
}

__global__ void __launch_bounds__(256, 2) decoder_hmma(const float* __restrict__ bias,
                                                       float* __restrict__ out,
                                                       int mblk0) {
    extern __shared__ __align__(16) char smem[];
    float* sbias = (float*)smem;
    const uint32_t D0 = s2u(smem) + 512;
    const int tid = threadIdx.x;
    const int wid = tid >> 5, lid = tid & 31;
    const int m0 = (blockIdx.x + mblk0) * 128, n0 = blockIdx.y * 128;
    const int wm = wid >> 1, wn = wid & 1;

    if (tid < 128) sbias[tid] = bias[n0 + tid];

    const char* Ag = (const char*)(g_Acat + (size_t)m0 * KA);
    const char* Bg = (const char*)(g_Bcat + (size_t)n0 * KB);
    const int r_ = tid >> 2, seg = tid & 3;

    float acc[2][8][4];
#pragma unroll
    for (int i = 0; i < 2; i++)
#pragma unroll
        for (int j = 0; j < 8; j++)
#pragma unroll
            for (int q = 0; q < 4; q++) acc[i][j][q] = 0.f;

#pragma unroll
    for (int s = 0; s < DEC_STAGES - 1; s++) {
        dec_load(D0 + s*DEC_STG_BYTES, Ag, Bg, s, r_, seg);
        cp_commit();
    }

    const int quad = lid >> 3, r8 = lid & 7;
    const uint32_t a_row = wm*32 + (quad & 1)*8 + r8;
    const uint32_t a_kb  = (quad >> 1) * 16;
    const uint32_t b_row = wn*64 + (quad >> 1)*8 + r8;
    const uint32_t b_kb  = (quad & 1) * 16;

    for (int kc = 0; kc < DEC_NCHUNK; kc++) {
        const int s = kc & (DEC_STAGES - 1);
        cp_wait<DEC_STAGES - 2>();
        __syncthreads();
        if (kc + DEC_STAGES - 1 < DEC_NCHUNK) {
            dec_load(D0 + ((kc + DEC_STAGES - 1) & (DEC_STAGES - 1))*DEC_STG_BYTES,
                     Ag, Bg, kc + DEC_STAGES - 1, r_, seg);
        }
        cp_commit();

        const uint32_t sA = D0 + s * DEC_STG_BYTES;
        const uint32_t sB = sA + 10240;
#pragma unroll
        for (int kk = 0; kk < 2; kk++) {
            uint32_t A0[4], A1[4], Bf[4][4];
            uint32_t aaddr = sA + a_row*80 + kk*32 + a_kb;
            ldmx4(A0, aaddr);
            ldmx4(A1, aaddr + 16*80);
            uint32_t baddr = sB + b_row*80 + kk*32 + b_kb;
#pragma unroll
            for (int p = 0; p < 4; p++) ldmx4(Bf[p], baddr + p*16*80);
#pragma unroll
            for (int ni = 0; ni < 8; ni++) {
                uint32_t b0 = Bf[ni >> 1][(ni & 1)*2 + 0];
                uint32_t b1 = Bf[ni >> 1][(ni & 1)*2 + 1];
                mma16816(acc[0][ni], A0, b0, b1);
                mma16816(acc[1][ni], A1, b0, b1);
            }
        }
    }
    cp_wait<0>();

    const int mrow0 = m0 + wm*32 + (lid >> 2);
    const int ncol0 = wn*64 + 2*(lid & 3);
#pragma unroll
    for (int mi = 0; mi < 2; mi++) {
        int mA = mrow0 + mi*16, mB = mA + 8;
        float* oA = out + (size_t)((mA & 15)*SEQLEN + (mA >> 4)) * VOCAB + n0;
        float* oB = out + (size_t)((mB & 15)*SEQLEN + (mB >> 4)) * VOCAB + n0;
#pragma unroll
        for (int ni = 0; ni < 8; ni++) {
            int nn = ncol0 + ni*8;
            float2 vA = make_float2(acc[mi][ni][0] + sbias[nn], acc[mi][ni][1] + sbias[nn+1]);
            float2 vB = make_float2(acc[mi][ni][2] + sbias[nn], acc[mi][ni][3] + sbias[nn+1]);
            *(float2*)(oA + nn) = vA;
            *(float2*)(oB + nn) = vB;
        }
    }
}

// ======================= launch ============================================
extern "C" void kernel_launch(void* const* d_in, const int* in_sizes, int n_in,
                              void* d_out, int out_size) {
    const int*   inp = (const int*)d_in[0];
    const float* emb = (const float*)d_in[1];
    const float* A   = (const float*)d_in[2];
    const float* B   = (const float*)d_in[3];
    const float* C   = (const float*)d_in[4];
    const float* U   = (const float*)d_in[5];
    const float* V   = (const float*)d_in[6];
    const float* dv  = (const float*)d_in[7];
    const float* Wd  = (const float*)d_in[8];
    const float* bd  = (const float*)d_in[9];
    float* out = (float*)d_out;

    // one-time stream/event setup (first call happens outside graph capture)
    static cudaStream_t sHi = nullptr, sLo = nullptr;
    static cudaEvent_t ev0, evR[NCHUNKS], evEnd;
    if (sHi == nullptr) {
        int prLo, prHi;
        cudaDeviceGetStreamPriorityRange(&prLo, &prHi);
        cudaStreamCreateWithPriority(&sHi, cudaStreamNonBlocking, prHi);
        cudaStreamCreateWithPriority(&sLo, cudaStreamNonBlocking, prLo);
        cudaEventCreateWithFlags(&ev0, cudaEventDisableTiming);
        for (int i = 0; i < NCHUNKS; i++)
            cudaEventCreateWithFlags(&evR[i], cudaEventDisableTiming);
        cudaEventCreateWithFlags(&evEnd, cudaEventDisableTiming);
        cudaFuncSetAttribute(rnn_kernel, cudaFuncAttributeMaxDynamicSharedMemorySize,
                             RNN_SMEM_BYTES);
        cudaFuncSetAttribute(decoder_hmma, cudaFuncAttributeMaxDynamicSharedMemorySize,
                             DEC_SMEM);
    }

    // fork both worker streams from the capture-origin stream
    cudaEventRecord(ev0, 0);
    cudaStreamWaitEvent(sHi, ev0, 0);
    cudaStreamWaitEvent(sLo, ev0, 0);

    // low stream: W conversion (needed before first decoder chunk)
    conv_W<<<dim3(VOCAB/32, HID/32), 256, 0, sLo>>>(Wd);

    // high stream: barrier reset, precompute, then chunked recurrence
    reset_bar<<<1, 1, 0, sHi>>>();
    dim3 gXU(NTOK/64, HID/64);
    gather_gemm<HID, true><<<gXU, 256, 0, sHi>>>(inp, emb, U, dv);
    dim3 gXB(NTOK/64, RANK/64);
    gather_gemm<RANK, false><<<gXB, 256, 0, sHi>>>(inp, emb, B, nullptr);

    for (int cch = 0; cch < NCHUNKS; cch++) {
        unsigned bar_base = (unsigned)cch * BARS_PER_CHUNK * RNN_BLOCKS;
        rnn_kernel<<<RNN_BLOCKS, 256, RNN_SMEM_BYTES, sHi>>>(
            A, C, V, cch*STEPS_PER_CHUNK, (cch + 1)*STEPS_PER_CHUNK, bar_base);
        cudaEventRecord(evR[cch], sHi);
    }

    // low stream: decoder chunks, each gated on its RNN chunk
    for (int cch = 0; cch < NCHUNKS; cch++) {
        cudaStreamWaitEvent(sLo, evR[cch], 0);
        decoder_hmma<<<dim3((NTOK/128)/NCHUNKS, VOCAB/128), 256, DEC_SMEM, sLo>>>(
            bd, out, cch * ((NTOK/128)/NCHUNKS));
    }

    // join both streams back to the origin stream
    cudaEventRecord(evEnd, sLo);
    cudaStreamWaitEvent(0, evR[NCHUNKS-1], 0);
    cudaStreamWaitEvent(0, evEnd, 0);
}